// round 17
// baseline (speedup 1.0000x reference)
#include <cuda_runtime.h>
#include <cstdint>
#include <math.h>

// Problem constants
#define BB 1024
#define TT 512
#define II 64
#define HH 32
#define OUT_OFFSET (BB * TT)      // h_last written after outs

#define NWARP 4                    // warps per block
#define NBLK  128                  // 128 * 4 warps * 2 batches = 1024

typedef unsigned long long u64;
typedef unsigned int u32;

// ---- b64-domain f32x2 helpers (aligned pairs, no marshaling MOVs) ----
__device__ __forceinline__ u64 pack2(float lo, float hi) {
    u64 r; asm("mov.b64 %0, {%1, %2};" : "=l"(r) : "f"(lo), "f"(hi)); return r;
}
__device__ __forceinline__ void unpack2(float& lo, float& hi, u64 v) {
    asm("mov.b64 {%0, %1}, %2;" : "=f"(lo), "=f"(hi) : "l"(v));
}
__device__ __forceinline__ u64 ffma2(u64 a, u64 b, u64 c) {
    u64 d; asm("fma.rn.f32x2 %0, %1, %2, %3;" : "=l"(d) : "l"(a), "l"(b), "l"(c));
    return d;
}
__device__ __forceinline__ u64 fadd2(u64 a, u64 b) {
    u64 d; asm("add.rn.f32x2 %0, %1, %2;" : "=l"(d) : "l"(a), "l"(b)); return d;
}
__device__ __forceinline__ float fast_tanh(float x) {
    float r; asm("tanh.approx.f32 %0, %1;" : "=f"(r) : "f"(x)); return r;
}
// load 2 consecutive u64 pairs from shared
__device__ __forceinline__ void lds2(u64& q0, u64& q1, u32 addr) {
    asm volatile("ld.shared.v2.u64 {%0,%1}, [%2];" : "=l"(q0), "=l"(q1) : "r"(addr));
}

// ---------------------------------------------------------------------------
// Fused RNN, 2-batches-per-warp with K-split halves.
//  lane = g*16 + sl:  g = K-half (0:[0,32), 1:[32,64)),  sl -> columns 2sl,2sl+1
//  Each lane computes partial dots (its K-half) for BOTH batches; one
//  shfl.xor(16) per step combines halves (x-proj partial rides along since
//  h-dot accumulates onto the previous step's x partial accumulators).
//  After exchange: lanes 0-15 own batch A's h pair, lanes 16-31 batch B's.
//  x rows stream through the verified 8-deep smem ring (one per batch).
//  Per-batch smem broadcast bytes are HALVED (16-lane replication, not 32).
// Grid: 128 blocks x 4 warps = 512 warps = 1 warp/SMSP on 128 SMs.
// ---------------------------------------------------------------------------
__global__ __launch_bounds__(NWARP * 32, 1) void rnn_fused2_kernel(
    const float* __restrict__ x,
    const float* __restrict__ h0,
    const float* __restrict__ W_ih,
    const float* __restrict__ b_ih,
    const float* __restrict__ W_hh,
    const float* __restrict__ b_hh,
    const float* __restrict__ W_out,
    const float* __restrict__ b_out,
    float* __restrict__ out)
{
    __shared__ __align__(16) u64   sx[NWARP][2][8][32];  // x rings: [batch][slot][pair]
    __shared__ __align__(16) u64   hs[NWARP][2][32];     // h pairs: [buf][lane]
    __shared__ float cmat[NWARP][2][8][17];              // out-dot: [batch][step][sl]

    const int lane = threadIdx.x & 31;
    const int wid  = threadIdx.x >> 5;
    const int g    = lane >> 4;        // K-half
    const int sl   = lane & 15;        // column pair index
    const int bA   = (blockIdx.x * NWARP + wid) * 2;
    const int bB   = bA + 1;
    const int myb  = g ? bB : bA;      // batch owned after the exchange

    // ---- weights: rows 2sl, 2sl+1, this lane's K-half, as u64 pairs ----
    u64 wx0[16], wx1[16];              // W_ih
    {
        const u64* r0 = reinterpret_cast<const u64*>(W_ih + (2 * sl)     * II) + 16 * g;
        const u64* r1 = reinterpret_cast<const u64*>(W_ih + (2 * sl + 1) * II) + 16 * g;
#pragma unroll
        for (int m = 0; m < 16; ++m) { wx0[m] = r0[m]; wx1[m] = r1[m]; }
    }
    u64 wh0[8], wh1[8];                // W_hh
    {
        const u64* r0 = reinterpret_cast<const u64*>(W_hh + (2 * sl)     * HH) + 8 * g;
        const u64* r1 = reinterpret_cast<const u64*>(W_hh + (2 * sl + 1) * HH) + 8 * g;
#pragma unroll
        for (int m = 0; m < 8; ++m) { wh0[m] = r0[m]; wh1[m] = r1[m]; }
    }
    // bias folded into x partials, only on the g==0 half (avoid double count)
    const float bias0 = g ? 0.f : (b_ih[2 * sl]     + b_hh[2 * sl]);
    const float bias1 = g ? 0.f : (b_ih[2 * sl + 1] + b_hh[2 * sl + 1]);
    const u64 bias0_2 = pack2(bias0, 0.f);
    const u64 bias1_2 = pack2(bias1, 0.f);
    const float wo0 = W_out[2 * sl], wo1 = W_out[2 * sl + 1];
    const float bout = b_out[0];

    // smem byte addresses
    const u32 sxA = (u32)__cvta_generic_to_shared(&sx[wid][0][0][0]);
    const u32 sxB = sxA + 8 * 32 * 8;                  // 2048B per ring
    const u32 hsb = (u32)__cvta_generic_to_shared(&hs[wid][0][0]);

    const u64* xrA = reinterpret_cast<const u64*>(x + (size_t)bA * TT * II);
    const u64* xrB = reinterpret_cast<const u64*>(x + (size_t)bB * TT * II);

    // ---- prologue: rows 0..7 staged, rows 8..11 in pre regs ----
#pragma unroll
    for (int i = 0; i < 8; ++i) {
        sx[wid][0][i][lane] = xrA[i * 32 + lane];
        sx[wid][1][i][lane] = xrB[i * 32 + lane];
    }
    u64 preA[4], preB[4];
#pragma unroll
    for (int i = 0; i < 4; ++i) {
        preA[i] = xrA[(8 + i) * 32 + lane];
        preB[i] = xrB[(8 + i) * 32 + lane];
    }

    // h0 pairs: hs[0][lane] = pair sl of batch myb
    hs[wid][0][lane] = reinterpret_cast<const u64*>(h0 + myb * HH)[sl];
    __syncwarp();

    // xp partial accumulators [A0a,A0b, A1a,A1b, B0a,B0b, B1a,B1b]
    u64 xp[8];
    // --- x-dot of row 0 into xp (prologue) ---
    {
        xp[0] = bias0_2; xp[1] = 0ull; xp[2] = bias1_2; xp[3] = 0ull;
        xp[4] = bias0_2; xp[5] = 0ull; xp[6] = bias1_2; xp[7] = 0ull;
        const u32 baseA = sxA + g * 128;
        const u32 baseB = sxB + g * 128;
#pragma unroll
        for (int i = 0; i < 8; ++i) {
            u64 a0, a1, b0, b1;
            lds2(a0, a1, baseA + i * 16);
            lds2(b0, b1, baseB + i * 16);
            xp[0] = ffma2(a0, wx0[2 * i], xp[0]);
            xp[1] = ffma2(a1, wx0[2 * i + 1], xp[1]);
            xp[2] = ffma2(a0, wx1[2 * i], xp[2]);
            xp[3] = ffma2(a1, wx1[2 * i + 1], xp[3]);
            xp[4] = ffma2(b0, wx0[2 * i], xp[4]);
            xp[5] = ffma2(b1, wx0[2 * i + 1], xp[5]);
            xp[6] = ffma2(b0, wx1[2 * i], xp[6]);
            xp[7] = ffma2(b1, wx1[2 * i + 1], xp[7]);
        }
    }

    float* outb = out;
    float h0f = 0.f, h1f = 0.f;   // my batch's h pair (post-exchange)

    for (int t0 = 0; t0 < TT; t0 += 8) {
#pragma unroll
        for (int u = 0; u < 8; ++u) {
            const int t = t0 + u;

            // stage row t+8 into slot u (dead since step t-1's syncwarp)
            sx[wid][0][u][lane] = preA[u & 3];
            sx[wid][1][u][lane] = preB[u & 3];
            {   // prefetch row t+12 (clamped; surplus unused)
                int r12 = t + 12; if (r12 > TT - 1) r12 = TT - 1;
                preA[u & 3] = xrA[r12 * 32 + lane];
                preB[u & 3] = xrB[r12 * 32 + lane];
            }

            // --- x-dot of row t+1 (slot (u+1)&7, staged 7 syncwarps ago) ---
            u64 xn[8];
            xn[0] = bias0_2; xn[1] = 0ull; xn[2] = bias1_2; xn[3] = 0ull;
            xn[4] = bias0_2; xn[5] = 0ull; xn[6] = bias1_2; xn[7] = 0ull;
            {
                const u32 so = ((u + 1) & 7) * 256 + g * 128;
#pragma unroll
                for (int i = 0; i < 8; ++i) {
                    u64 a0, a1, b0, b1;
                    lds2(a0, a1, sxA + so + i * 16);
                    lds2(b0, b1, sxB + so + i * 16);
                    xn[0] = ffma2(a0, wx0[2 * i], xn[0]);
                    xn[1] = ffma2(a1, wx0[2 * i + 1], xn[1]);
                    xn[2] = ffma2(a0, wx1[2 * i], xn[2]);
                    xn[3] = ffma2(a1, wx1[2 * i + 1], xn[3]);
                    xn[4] = ffma2(b0, wx0[2 * i], xn[4]);
                    xn[5] = ffma2(b1, wx0[2 * i + 1], xn[5]);
                    xn[6] = ffma2(b0, wx1[2 * i], xn[6]);
                    xn[7] = ffma2(b1, wx1[2 * i + 1], xn[7]);
                }
            }

            // --- h-dot of step t accumulated onto xp (the exchange below
            //     then combines x and h partials at once) ---
            {
                const u32 hbA = hsb + (u & 1) * 256 + g * 64;        // batch A half
                const u32 hbB = hbA + 128;                           // batch B half
#pragma unroll
                for (int i = 0; i < 4; ++i) {
                    u64 a0, a1, b0, b1;
                    lds2(a0, a1, hbA + i * 16);
                    lds2(b0, b1, hbB + i * 16);
                    xp[0] = ffma2(a0, wh0[2 * i], xp[0]);
                    xp[1] = ffma2(a1, wh0[2 * i + 1], xp[1]);
                    xp[2] = ffma2(a0, wh1[2 * i], xp[2]);
                    xp[3] = ffma2(a1, wh1[2 * i + 1], xp[3]);
                    xp[4] = ffma2(b0, wh0[2 * i], xp[4]);
                    xp[5] = ffma2(b1, wh0[2 * i + 1], xp[5]);
                    xp[6] = ffma2(b0, wh1[2 * i], xp[6]);
                    xp[7] = ffma2(b1, wh1[2 * i + 1], xp[7]);
                }
            }

            // --- merge pair-accs to scalars: sA0,sA1,sB0,sB1 (K-half partials) ---
            float sA0, sA1, sB0, sB1;
            {
                float lo, hi;
                u64 m0 = fadd2(xp[0], xp[1]); unpack2(lo, hi, m0); sA0 = lo + hi;
                u64 m1 = fadd2(xp[2], xp[3]); unpack2(lo, hi, m1); sA1 = lo + hi;
                u64 m2 = fadd2(xp[4], xp[5]); unpack2(lo, hi, m2); sB0 = lo + hi;
                u64 m3 = fadd2(xp[6], xp[7]); unpack2(lo, hi, m3); sB1 = lo + hi;
            }

            // --- exchange halves: lane keeps its own batch, sends the other ---
            const float send0 = g ? sA0 : sB0;
            const float send1 = g ? sA1 : sB1;
            const float r0 = __shfl_xor_sync(0xffffffffu, send0, 16);
            const float r1 = __shfl_xor_sync(0xffffffffu, send1, 16);
            const float s0 = (g ? sB0 : sA0) + r0;
            const float s1 = (g ? sB1 : sA1) + r1;

            // --- activation + output contribution (my batch, cols 2sl,2sl+1) ---
            h0f = fast_tanh(s0);
            h1f = fast_tanh(s1);
            hs[wid][(u + 1) & 1][lane] = pack2(h0f, h1f);           // feed step t+1
            cmat[wid][g][u][sl] = fmaf(h1f, wo1, h0f * wo0);
            __syncwarp();

            // carry x partials for step t+1
#pragma unroll
            for (int k = 0; k < 8; ++k) xp[k] = xn[k];
        }

        // --- flush 8 steps x 2 batches of output dots ---
        {
            const int r  = lane & 15;        // row: batch = r>>3, step = r&7
            const int h2 = lane >> 4;        // which 8-column half to sum
            const float* row = &cmat[wid][r >> 3][r & 7][h2 * 8];
            float v = ((row[0] + row[1]) + (row[2] + row[3])) +
                      ((row[4] + row[5]) + (row[6] + row[7]));
            v += __shfl_xor_sync(0xffffffffu, v, 16);
            if (lane < 16) {
                const int ob = (r >> 3) ? bB : bA;
                outb[(size_t)ob * TT + t0 + (r & 7)] = v + bout;
            }
            __syncwarp();   // protect cmat reuse next outer iteration
        }
    }

    // h_last [1, B, H]: lane writes its batch's pair (2sl, 2sl+1)
    reinterpret_cast<u64*>(out + OUT_OFFSET + myb * HH)[sl] = pack2(h0f, h1f);
}

extern "C" void kernel_launch(void* const* d_in, const int* in_sizes, int n_in,
                              void* d_out, int out_size) {
    const float* x     = (const float*)d_in[0];
    const float* h0    = (const float*)d_in[1];
    const float* W_ih  = (const float*)d_in[2];
    const float* b_ih  = (const float*)d_in[3];
    const float* W_hh  = (const float*)d_in[4];
    const float* b_hh  = (const float*)d_in[5];
    const float* W_out = (const float*)d_in[6];
    const float* b_out = (const float*)d_in[7];
    float* out = (float*)d_out;

    (void)in_sizes; (void)n_in; (void)out_size;

    rnn_fused2_kernel<<<NBLK, NWARP * 32>>>(x, h0, W_ih, b_ih, W_hh, b_hh,
                                            W_out, b_out, out);
}